// round 2
// baseline (speedup 1.0000x reference)
#include <cuda_runtime.h>
#include <math.h>

#define S_LEN 2048
#define BATCH 4
#define EMB   1024
#define NH    16
#define HD    64
#define NTOK  (BATCH * S_LEN)   // 8192

// Scratch (device globals: allocation-free per harness rules). 4 x 32 MiB.
__device__ float g_Q[NTOK * EMB];
__device__ float g_K[NTOK * EMB];
__device__ float g_V[NTOK * EMB];
__device__ float g_O[NTOK * EMB];

// ---------------------------------------------------------------------------
// GEMM: C[M,N] = A[M,K] @ B[N,K]^T   (both row-major, K contiguous -> NT gemm)
// 64x64 block tile, 16-deep K slice, 256 threads, 4x4 micro-tile per thread.
// Smem tiles stored transposed [k][m] so the inner loop reads are float4,
// conflict-free broadcasts.
// ---------------------------------------------------------------------------
__global__ __launch_bounds__(256) void gemm_nt64(
    const float* __restrict__ A, const float* __restrict__ B,
    float* __restrict__ C, int M, int N, int K)
{
    __shared__ float As[16 * 64];
    __shared__ float Bs[16 * 64];

    const int tid = threadIdx.x;
    const int tx = tid & 15, ty = tid >> 4;
    const int r0 = ty * 4, c0 = tx * 4;
    const int m0 = blockIdx.y * 64, n0 = blockIdx.x * 64;
    const int lrow = tid >> 2;          // 0..63
    const int lk   = (tid & 3) * 4;     // 0,4,8,12

    float acc[4][4] = {};

    for (int k0 = 0; k0 < K; k0 += 16) {
        float4 av = *(const float4*)(A + (size_t)(m0 + lrow) * K + k0 + lk);
        float4 bv = *(const float4*)(B + (size_t)(n0 + lrow) * K + k0 + lk);
        As[(lk + 0) * 64 + lrow] = av.x;
        As[(lk + 1) * 64 + lrow] = av.y;
        As[(lk + 2) * 64 + lrow] = av.z;
        As[(lk + 3) * 64 + lrow] = av.w;
        Bs[(lk + 0) * 64 + lrow] = bv.x;
        Bs[(lk + 1) * 64 + lrow] = bv.y;
        Bs[(lk + 2) * 64 + lrow] = bv.z;
        Bs[(lk + 3) * 64 + lrow] = bv.w;
        __syncthreads();

        #pragma unroll
        for (int kk = 0; kk < 16; kk++) {
            float4 a4 = *(const float4*)&As[kk * 64 + r0];
            float4 b4 = *(const float4*)&Bs[kk * 64 + c0];
            float a[4] = {a4.x, a4.y, a4.z, a4.w};
            float b[4] = {b4.x, b4.y, b4.z, b4.w};
            #pragma unroll
            for (int i = 0; i < 4; i++)
                #pragma unroll
                for (int j = 0; j < 4; j++)
                    acc[i][j] += a[i] * b[j];
        }
        __syncthreads();
    }

    #pragma unroll
    for (int i = 0; i < 4; i++) {
        float4 o = {acc[i][0], acc[i][1], acc[i][2], acc[i][3]};
        *(float4*)(C + (size_t)(m0 + r0 + i) * N + n0 + c0) = o;
    }
}

// ---------------------------------------------------------------------------
// Flash attention, 64x64 tiles, causal + pad mask, online softmax.
// Q,K,V scratch layout: [B*S, EMB] with head h occupying columns h*64..h*64+63.
// Smem: Qs[q][d], Kt[d][k] (transposed), Vs[k][d], Ss[q][k]; pitch 68 floats
// (16B-aligned rows, bank-conflict-breaking).
// ---------------------------------------------------------------------------
#define FP 68
#define FLASH_SMEM ((4 * 64 * FP + 4 * 64) * (int)sizeof(float))  // 70656 B

__global__ __launch_bounds__(256) void flash64(
    const float* __restrict__ Q, const float* __restrict__ Kg,
    const float* __restrict__ V, const int* __restrict__ am,
    float* __restrict__ O)
{
    extern __shared__ float sm[];
    float* Qs   = sm;                 // 64 x FP
    float* Kt   = Qs + 64 * FP;       // 64(d) x FP (cols = k index)
    float* Vs   = Kt + 64 * FP;       // 64(k) x FP (cols = d)
    float* Ss   = Vs + 64 * FP;       // 64(q) x FP (cols = k)
    float* m_s  = Ss + 64 * FP;       // 64
    float* l_s  = m_s + 64;           // 64
    float* al_s = l_s + 64;           // 64
    float* madd = al_s + 64;          // 64 (pad-mask additive)

    const int tid = threadIdx.x;
    const int qt = blockIdx.x, h = blockIdx.y, b = blockIdx.z;
    const int q0 = qt * 64;
    const int tx = tid & 15, ty = tid >> 4;
    const int r0 = ty * 4, c0 = tx * 4;
    const size_t rowbase = (size_t)b * S_LEN;
    const int colbase = h * HD;
    const float scale = 0.125f;   // 1/sqrt(64)

    // Load Q tile
    #pragma unroll
    for (int it = 0; it < 4; it++) {
        int lin = it * 256 + tid;
        int row = lin >> 4;
        int cc  = (lin & 15) * 4;
        float4 v = *(const float4*)(Q + (rowbase + q0 + row) * EMB + colbase + cc);
        *(float4*)&Qs[row * FP + cc] = v;
    }
    if (tid < 64) { m_s[tid] = -1e30f; l_s[tid] = 0.0f; }

    float acc[4][4] = {};

    for (int kt = 0; kt <= qt; kt++) {
        const int k0 = kt * 64;
        __syncthreads();  // prev iteration's PV done; Q/m/l init visible (1st iter)

        // Load K (transposed into Kt[d][k]) and V (direct Vs[k][d])
        #pragma unroll
        for (int it = 0; it < 4; it++) {
            int lin = it * 256 + tid;
            int row = lin >> 4;
            int cc  = (lin & 15) * 4;
            float4 kv = *(const float4*)(Kg + (rowbase + k0 + row) * EMB + colbase + cc);
            Kt[(cc + 0) * FP + row] = kv.x;
            Kt[(cc + 1) * FP + row] = kv.y;
            Kt[(cc + 2) * FP + row] = kv.z;
            Kt[(cc + 3) * FP + row] = kv.w;
            float4 vv = *(const float4*)(V + (rowbase + k0 + row) * EMB + colbase + cc);
            *(float4*)&Vs[row * FP + cc] = vv;
        }
        if (tid < 64) madd[tid] = am[rowbase + k0 + tid] ? 0.0f : -1e30f;
        __syncthreads();

        // S = Q @ K^T (raw; scale applied in softmax scan)
        float s[4][4] = {};
        #pragma unroll
        for (int d = 0; d < 64; d++) {
            float4 k4 = *(const float4*)&Kt[d * FP + c0];
            float kb[4] = {k4.x, k4.y, k4.z, k4.w};
            #pragma unroll
            for (int i = 0; i < 4; i++) {
                float qv = Qs[(r0 + i) * FP + d];
                #pragma unroll
                for (int j = 0; j < 4; j++) s[i][j] += qv * kb[j];
            }
        }
        #pragma unroll
        for (int i = 0; i < 4; i++)
            #pragma unroll
            for (int j = 0; j < 4; j++)
                Ss[(r0 + i) * FP + c0 + j] = s[i][j];
        __syncthreads();

        // Online softmax: 4 lanes per row (lanes aligned within warp)
        {
            const int row = tid >> 2;
            const int l4  = tid & 3;
            const bool diag = (kt == qt);
            float vals[16];
            float mx = -1e30f;
            #pragma unroll
            for (int t = 0; t < 16; t++) {
                int col = l4 + t * 4;
                float v = Ss[row * FP + col] * scale + madd[col];
                if (diag && (k0 + col) > (q0 + row)) v = -1e30f;
                vals[t] = v;
                mx = fmaxf(mx, v);
            }
            mx = fmaxf(mx, __shfl_xor_sync(0xffffffffu, mx, 1));
            mx = fmaxf(mx, __shfl_xor_sync(0xffffffffu, mx, 2));
            float mprev = m_s[row];
            float mnew  = fmaxf(mprev, mx);
            float sum = 0.0f;
            #pragma unroll
            for (int t = 0; t < 16; t++) {
                int col = l4 + t * 4;
                float p = __expf(vals[t] - mnew);
                Ss[row * FP + col] = p;
                sum += p;
            }
            sum += __shfl_xor_sync(0xffffffffu, sum, 1);
            sum += __shfl_xor_sync(0xffffffffu, sum, 2);
            float alpha = __expf(mprev - mnew);
            if (l4 == 0) {
                m_s[row]  = mnew;
                l_s[row]  = l_s[row] * alpha + sum;
                al_s[row] = alpha;
            }
        }
        __syncthreads();

        // Rescale accumulator, then O += P @ V
        #pragma unroll
        for (int i = 0; i < 4; i++) {
            float al = al_s[r0 + i];
            #pragma unroll
            for (int j = 0; j < 4; j++) acc[i][j] *= al;
        }
        #pragma unroll
        for (int k = 0; k < 64; k++) {
            float4 v4 = *(const float4*)&Vs[k * FP + c0];
            float vb[4] = {v4.x, v4.y, v4.z, v4.w};
            #pragma unroll
            for (int i = 0; i < 4; i++) {
                float p = Ss[(r0 + i) * FP + k];
                #pragma unroll
                for (int j = 0; j < 4; j++) acc[i][j] += p * vb[j];
            }
        }
    }

    __syncthreads();
    #pragma unroll
    for (int i = 0; i < 4; i++) {
        float inv = 1.0f / l_s[r0 + i];
        float4 o = {acc[i][0] * inv, acc[i][1] * inv, acc[i][2] * inv, acc[i][3] * inv};
        *(float4*)(O + (rowbase + q0 + r0 + i) * EMB + colbase + c0) = o;
    }
}

// ---------------------------------------------------------------------------
extern "C" void kernel_launch(void* const* d_in, const int* in_sizes, int n_in,
                              void* d_out, int out_size)
{
    const float* x  = (const float*)d_in[0];
    const int*   am = (const int*)d_in[1];
    const float* wq = (const float*)d_in[2];
    const float* wk = (const float*)d_in[3];
    const float* wv = (const float*)d_in[4];
    const float* wo = (const float*)d_in[5];
    float* out = (float*)d_out;

    float *Qp, *Kp, *Vp, *Op;
    cudaGetSymbolAddress((void**)&Qp, g_Q);
    cudaGetSymbolAddress((void**)&Kp, g_K);
    cudaGetSymbolAddress((void**)&Vp, g_V);
    cudaGetSymbolAddress((void**)&Op, g_O);
    cudaFuncSetAttribute(flash64, cudaFuncAttributeMaxDynamicSharedMemorySize,
                         FLASH_SMEM);

    dim3 ggrid(EMB / 64, NTOK / 64);
    gemm_nt64<<<ggrid, 256>>>(x, wq, Qp, NTOK, EMB, EMB);
    gemm_nt64<<<ggrid, 256>>>(x, wk, Kp, NTOK, EMB, EMB);
    gemm_nt64<<<ggrid, 256>>>(x, wv, Vp, NTOK, EMB, EMB);

    flash64<<<dim3(S_LEN / 64, NH, BATCH), 256, FLASH_SMEM>>>(Qp, Kp, Vp, am, Op);

    gemm_nt64<<<ggrid, 256>>>(Op, wo, out, NTOK, EMB, EMB);
}

// round 7
// speedup vs baseline: 2.7422x; 2.7422x over previous
#include <cuda_runtime.h>
#include <cuda_bf16.h>
#include <cstdint>
#include <math.h>

#define S_LEN 2048
#define BATCH 4
#define EMB   1024
#define NH    16
#define HD    64
#define NTOK  (BATCH * S_LEN)   // 8192

// ---------------- scratch (device globals; no allocs allowed) --------------
__device__ __nv_bfloat16 g_xh[NTOK * EMB];
__device__ __nv_bfloat16 g_xl[NTOK * EMB];
__device__ __nv_bfloat16 g_wh[4][EMB * EMB];
__device__ __nv_bfloat16 g_wl[4][EMB * EMB];
__device__ __nv_bfloat16 g_Qh[NTOK * EMB];
__device__ __nv_bfloat16 g_Ql[NTOK * EMB];
__device__ __nv_bfloat16 g_Kh[NTOK * EMB];
__device__ __nv_bfloat16 g_Kl[NTOK * EMB];
__device__ __nv_bfloat16 g_Vh[NTOK * EMB];
__device__ __nv_bfloat16 g_Vl[NTOK * EMB];
__device__ __nv_bfloat16 g_Oh[NTOK * EMB];
__device__ __nv_bfloat16 g_Ol[NTOK * EMB];

// ---------------- helpers --------------------------------------------------
__device__ __forceinline__ uint32_t smem_u32(const void* p) {
    uint32_t a;
    asm("{ .reg .u64 t; cvta.to.shared.u64 t, %1; cvt.u32.u64 %0, t; }" : "=r"(a) : "l"(p));
    return a;
}
__device__ __forceinline__ void ldsm_x4(uint32_t a, uint32_t& r0, uint32_t& r1,
                                        uint32_t& r2, uint32_t& r3) {
    asm volatile("ldmatrix.sync.aligned.m8n8.x4.shared.b16 {%0,%1,%2,%3}, [%4];"
                 : "=r"(r0), "=r"(r1), "=r"(r2), "=r"(r3) : "r"(a));
}
__device__ __forceinline__ void ldsm_x4t(uint32_t a, uint32_t& r0, uint32_t& r1,
                                         uint32_t& r2, uint32_t& r3) {
    asm volatile("ldmatrix.sync.aligned.m8n8.x4.trans.shared.b16 {%0,%1,%2,%3}, [%4];"
                 : "=r"(r0), "=r"(r1), "=r"(r2), "=r"(r3) : "r"(a));
}
__device__ __forceinline__ void mma_bf16(float* d, const uint32_t* a,
                                         uint32_t b0, uint32_t b1) {
    asm volatile(
        "mma.sync.aligned.m16n8k16.row.col.f32.bf16.bf16.f32 "
        "{%0,%1,%2,%3}, {%4,%5,%6,%7}, {%8,%9}, {%0,%1,%2,%3};"
        : "+f"(d[0]), "+f"(d[1]), "+f"(d[2]), "+f"(d[3])
        : "r"(a[0]), "r"(a[1]), "r"(a[2]), "r"(a[3]), "r"(b0), "r"(b1));
}
__device__ __forceinline__ void split2(float x, float y, uint32_t& hi, uint32_t& lo) {
    __nv_bfloat162 h = __floats2bfloat162_rn(x, y);
    hi = *(uint32_t*)&h;
    __nv_bfloat162 l = __floats2bfloat162_rn(x - __bfloat162float(h.x),
                                             y - __bfloat162float(h.y));
    lo = *(uint32_t*)&l;
}

// ---------------------------------------------------------------------------
// split fp32 -> (hi, lo) bf16
// ---------------------------------------------------------------------------
__global__ __launch_bounds__(256) void split_k(
    const float* __restrict__ src, __nv_bfloat16* __restrict__ hi,
    __nv_bfloat16* __restrict__ lo, int n4)
{
    int i = blockIdx.x * 256 + threadIdx.x;
    if (i >= n4) return;
    float4 v = ((const float4*)src)[i];
    float x[4] = {v.x, v.y, v.z, v.w};
    __nv_bfloat16 h[4], l[4];
    #pragma unroll
    for (int j = 0; j < 4; j++) {
        h[j] = __float2bfloat16_rn(x[j]);
        l[j] = __float2bfloat16_rn(x[j] - __bfloat162float(h[j]));
    }
    ((uint2*)hi)[i] = *(uint2*)h;
    ((uint2*)lo)[i] = *(uint2*)l;
}

// ---------------------------------------------------------------------------
// mma.sync split-bf16 GEMM: C[M,N] = A[M,K] @ B[N,K]^T, M=8192, N=K=1024.
// CTA 128x128, K chunk 32, cp.async double-buffered, 8 warps (2m x 4n),
// warp tile 64x32. Output: fp32 (Cf) or bf16 hi/lo split (Ch/Cl).
// ---------------------------------------------------------------------------
#define GP 40                         // smem pitch in halves (32 + 8 pad)
#define GTILE_H (128 * GP)            // halves per tile (5120)
#define GSTAGE_H (4 * GTILE_H)        // Ah,Al,Bh,Bl  (20480 halves)
#define GEMM_SMEM (2 * GSTAGE_H * 2)  // 81920 bytes

__global__ __launch_bounds__(256) void gemm_tc(
    const __nv_bfloat16* __restrict__ Ah, const __nv_bfloat16* __restrict__ Al,
    const __nv_bfloat16* __restrict__ Bh, const __nv_bfloat16* __restrict__ Bl,
    float* __restrict__ Cf, __nv_bfloat16* __restrict__ Ch,
    __nv_bfloat16* __restrict__ Cl)
{
    extern __shared__ __nv_bfloat16 sm[];
    const uint32_t sb = smem_u32(sm);
    const int tid = threadIdx.x, lane = tid & 31, w = tid >> 5;
    const int wm = w & 1, wn = w >> 1;
    const int m0 = blockIdx.y * 128, n0 = blockIdx.x * 128;

    const __nv_bfloat16* srcs[4] = {Ah, Al, Bh, Bl};
    const int r0s[4] = {m0, m0, n0, n0};

    auto issue_loads = [&](int k0, int st) {
        #pragma unroll
        for (int i = 0; i < 8; i++) {
            int idx = i * 256 + tid;
            int t = idx >> 9, j = idx & 511;
            int row = j >> 2, c8 = (j & 3) * 8;
            const __nv_bfloat16* g = srcs[t] + (size_t)(r0s[t] + row) * EMB + k0 + c8;
            uint32_t s = sb + (st * GSTAGE_H + t * GTILE_H + row * GP + c8) * 2;
            asm volatile("cp.async.cg.shared.global [%0], [%1], 16;"
                         :: "r"(s), "l"(g) : "memory");
        }
        asm volatile("cp.async.commit_group;" ::: "memory");
    };

    issue_loads(0, 0);
    float acc[4][4][4] = {};

    for (int c = 0; c < 32; c++) {
        const int st = c & 1;
        if (c + 1 < 32) {
            issue_loads((c + 1) * 32, st ^ 1);
            asm volatile("cp.async.wait_group 1;" ::: "memory");
        } else {
            asm volatile("cp.async.wait_group 0;" ::: "memory");
        }
        __syncthreads();

        const uint32_t abase = sb + (st * GSTAGE_H) * 2;
        const uint32_t bbase = sb + (st * GSTAGE_H + 2 * GTILE_H) * 2;
        #pragma unroll
        for (int kc = 0; kc < 2; kc++) {
            uint32_t af[4][4], alf[4][4], bf[2][4], blf[2][4];
            #pragma unroll
            for (int mt = 0; mt < 4; mt++) {
                int row = wm * 64 + mt * 16 + (lane & 15);
                uint32_t a = abase + (row * GP + kc * 16 + 8 * (lane >> 4)) * 2;
                ldsm_x4(a, af[mt][0], af[mt][1], af[mt][2], af[mt][3]);
                ldsm_x4(a + GTILE_H * 2, alf[mt][0], alf[mt][1], alf[mt][2], alf[mt][3]);
            }
            #pragma unroll
            for (int u = 0; u < 2; u++) {
                int row = wn * 32 + u * 16 + (lane & 7) + 8 * ((lane >> 3) & 1);
                uint32_t b = bbase + (row * GP + kc * 16 + 8 * (lane >> 4)) * 2;
                ldsm_x4(b, bf[u][0], bf[u][1], bf[u][2], bf[u][3]);
                ldsm_x4(b + GTILE_H * 2, blf[u][0], blf[u][1], blf[u][2], blf[u][3]);
            }
            #pragma unroll
            for (int mt = 0; mt < 4; mt++)
                #pragma unroll
                for (int u = 0; u < 2; u++) {
                    mma_bf16(acc[mt][2*u],   af[mt],  bf[u][0],  bf[u][2]);
                    mma_bf16(acc[mt][2*u],   af[mt],  blf[u][0], blf[u][2]);
                    mma_bf16(acc[mt][2*u],   alf[mt], bf[u][0],  bf[u][2]);
                    mma_bf16(acc[mt][2*u+1], af[mt],  bf[u][1],  bf[u][3]);
                    mma_bf16(acc[mt][2*u+1], af[mt],  blf[u][1], blf[u][3]);
                    mma_bf16(acc[mt][2*u+1], alf[mt], bf[u][1],  bf[u][3]);
                }
        }
        __syncthreads();
    }

    #pragma unroll
    for (int mt = 0; mt < 4; mt++) {
        int grow = m0 + wm * 64 + mt * 16 + (lane >> 2);
        #pragma unroll
        for (int nt = 0; nt < 4; nt++) {
            int gcol = n0 + wn * 32 + nt * 8 + 2 * (lane & 3);
            float* a = acc[mt][nt];
            if (Cf) {
                *(float2*)(Cf + (size_t)grow * EMB + gcol) = make_float2(a[0], a[1]);
                *(float2*)(Cf + (size_t)(grow + 8) * EMB + gcol) = make_float2(a[2], a[3]);
            } else {
                uint32_t h, l;
                split2(a[0], a[1], h, l);
                *(uint32_t*)(Ch + (size_t)grow * EMB + gcol) = h;
                *(uint32_t*)(Cl + (size_t)grow * EMB + gcol) = l;
                split2(a[2], a[3], h, l);
                *(uint32_t*)(Ch + (size_t)(grow + 8) * EMB + gcol) = h;
                *(uint32_t*)(Cl + (size_t)(grow + 8) * EMB + gcol) = l;
            }
        }
    }
}

// ---------------------------------------------------------------------------
// Flash attention on mma.sync, split-bf16 3-term everywhere.
// CTA: 128 q-rows x one (head, batch); 8 warps x 16 q-rows; 64-key tiles.
// Softmax lives in accumulator fragments (row = lane/4, quad shfl reduce).
// ---------------------------------------------------------------------------
#define FPH 72
#define FQ_H (128 * FPH)   // 9216 halves per Q tile
#define FK_H (64 * FPH)    // 4608 halves per K/V tile
#define FLASH_SMEM ((2 * FQ_H + 4 * FK_H) * 2 + 256)

__global__ __launch_bounds__(256) void flash_tc(
    const __nv_bfloat16* __restrict__ Qh, const __nv_bfloat16* __restrict__ Ql,
    const __nv_bfloat16* __restrict__ Kh, const __nv_bfloat16* __restrict__ Kl,
    const __nv_bfloat16* __restrict__ Vh, const __nv_bfloat16* __restrict__ Vl,
    const int* __restrict__ am,
    __nv_bfloat16* __restrict__ Oh, __nv_bfloat16* __restrict__ Ol)
{
    extern __shared__ __nv_bfloat16 sm[];
    const uint32_t sb = smem_u32(sm);
    __nv_bfloat16* sQh = sm;
    __nv_bfloat16* sQl = sm + FQ_H;
    __nv_bfloat16* sKh = sm + 2 * FQ_H;
    __nv_bfloat16* sKl = sKh + FK_H;
    __nv_bfloat16* sVh = sKl + FK_H;
    __nv_bfloat16* sVl = sVh + FK_H;
    float* madd = (float*)(sVl + FK_H);

    const int tid = threadIdx.x, lane = tid & 31, w = tid >> 5;
    const int q0 = blockIdx.x * 128;
    const size_t rowbase = (size_t)blockIdx.z * S_LEN;
    const int colbase = blockIdx.y * HD;

    // Q tile (hi + lo)
    #pragma unroll
    for (int i = 0; i < 4; i++) {
        int idx = i * 256 + tid;                 // 0..1023
        int row = idx >> 3, c8 = (idx & 7) * 8;
        size_t go = (rowbase + q0 + row) * EMB + colbase + c8;
        *(float4*)&sQh[row * FPH + c8] = *(const float4*)&Qh[go];
        *(float4*)&sQl[row * FPH + c8] = *(const float4*)&Ql[go];
    }

    float oacc[8][4] = {};
    float mr0 = -1e30f, mr1 = -1e30f, lr0 = 0.f, lr1 = 0.f;

    const uint32_t aQh = sb, aQl = sb + FQ_H * 2;
    const uint32_t aKh = sb + 2 * FQ_H * 2, aKl = aKh + FK_H * 2;
    const uint32_t aVh = aKl + FK_H * 2,    aVl = aVh + FK_H * 2;

    const int nkt = (q0 >> 6) + 2;
    for (int kt = 0; kt < nkt; kt++) {
        const int k0 = kt * 64;
        __syncthreads();
        #pragma unroll
        for (int i = 0; i < 8; i++) {
            int idx = i * 256 + tid;             // 0..2047
            int t = idx >> 9, j = idx & 511;
            int row = j >> 3, c8 = (j & 7) * 8;
            const __nv_bfloat16* g = (t == 0 ? Kh : t == 1 ? Kl : t == 2 ? Vh : Vl);
            __nv_bfloat16* d = (t == 0 ? sKh : t == 1 ? sKl : t == 2 ? sVh : sVl);
            *(float4*)&d[row * FPH + c8] =
                *(const float4*)&g[(rowbase + k0 + row) * EMB + colbase + c8];
        }
        if (tid < 64) madd[tid] = am[rowbase + k0 + tid] ? 0.f : -1e30f;
        __syncthreads();

        // ---- S = Q @ K^T (3-term split) ----
        float sacc[8][4] = {};
        #pragma unroll
        for (int kc = 0; kc < 4; kc++) {
            uint32_t qa[4], qla[4];
            {
                int row = w * 16 + (lane & 15);
                uint32_t a = (row * FPH + kc * 16 + 8 * (lane >> 4)) * 2;
                ldsm_x4(aQh + a, qa[0], qa[1], qa[2], qa[3]);
                ldsm_x4(aQl + a, qla[0], qla[1], qla[2], qla[3]);
            }
            #pragma unroll
            for (int np = 0; np < 4; np++) {
                int row = np * 16 + (lane & 7) + 8 * ((lane >> 3) & 1);
                uint32_t boff = (row * FPH + kc * 16 + 8 * (lane >> 4)) * 2;
                uint32_t kh[4], kl[4];
                ldsm_x4(aKh + boff, kh[0], kh[1], kh[2], kh[3]);
                ldsm_x4(aKl + boff, kl[0], kl[1], kl[2], kl[3]);
                mma_bf16(sacc[2*np],   qa,  kh[0], kh[2]);
                mma_bf16(sacc[2*np],   qa,  kl[0], kl[2]);
                mma_bf16(sacc[2*np],   qla, kh[0], kh[2]);
                mma_bf16(sacc[2*np+1], qa,  kh[1], kh[3]);
                mma_bf16(sacc[2*np+1], qa,  kl[1], kl[3]);
                mma_bf16(sacc[2*np+1], qla, kh[1], kh[3]);
            }
        }

        // ---- online softmax in fragments ----
        const int qrow = q0 + w * 16 + (lane >> 2);
        const bool needmask = (k0 + 63) > (q0 + w * 16);
        float mx0 = -1e30f, mx1 = -1e30f;
        #pragma unroll
        for (int t = 0; t < 8; t++) {
            int lc = t * 8 + 2 * (lane & 3);
            float ma0 = madd[lc], ma1 = madd[lc + 1];
            float s0 = sacc[t][0] * 0.125f + ma0;
            float s1 = sacc[t][1] * 0.125f + ma1;
            float s2 = sacc[t][2] * 0.125f + ma0;
            float s3 = sacc[t][3] * 0.125f + ma1;
            if (needmask) {
                int cg = k0 + lc;
                if (cg > qrow)         s0 = -1e30f;
                if (cg + 1 > qrow)     s1 = -1e30f;
                if (cg > qrow + 8)     s2 = -1e30f;
                if (cg + 1 > qrow + 8) s3 = -1e30f;
            }
            sacc[t][0] = s0; sacc[t][1] = s1; sacc[t][2] = s2; sacc[t][3] = s3;
            mx0 = fmaxf(mx0, fmaxf(s0, s1));
            mx1 = fmaxf(mx1, fmaxf(s2, s3));
        }
        mx0 = fmaxf(mx0, __shfl_xor_sync(0xffffffffu, mx0, 1));
        mx0 = fmaxf(mx0, __shfl_xor_sync(0xffffffffu, mx0, 2));
        mx1 = fmaxf(mx1, __shfl_xor_sync(0xffffffffu, mx1, 1));
        mx1 = fmaxf(mx1, __shfl_xor_sync(0xffffffffu, mx1, 2));
        float mn0 = fmaxf(mr0, mx0), mn1 = fmaxf(mr1, mx1);
        float al0 = __expf(mr0 - mn0), al1 = __expf(mr1 - mn1);
        mr0 = mn0; mr1 = mn1;
        float sm0 = 0.f, sm1 = 0.f;
        #pragma unroll
        for (int t = 0; t < 8; t++) {
            float p0 = __expf(sacc[t][0] - mn0);
            float p1 = __expf(sacc[t][1] - mn0);
            float p2 = __expf(sacc[t][2] - mn1);
            float p3 = __expf(sacc[t][3] - mn1);
            sacc[t][0] = p0; sacc[t][1] = p1; sacc[t][2] = p2; sacc[t][3] = p3;
            sm0 += p0 + p1; sm1 += p2 + p3;
        }
        sm0 += __shfl_xor_sync(0xffffffffu, sm0, 1);
        sm0 += __shfl_xor_sync(0xffffffffu, sm0, 2);
        sm1 += __shfl_xor_sync(0xffffffffu, sm1, 1);
        sm1 += __shfl_xor_sync(0xffffffffu, sm1, 2);
        lr0 = lr0 * al0 + sm0;
        lr1 = lr1 * al1 + sm1;
        #pragma unroll
        for (int t = 0; t < 8; t++) {
            oacc[t][0] *= al0; oacc[t][1] *= al0;
            oacc[t][2] *= al1; oacc[t][3] *= al1;
        }

        // ---- O += P @ V (3-term split; P stays in registers) ----
        #pragma unroll
        for (int t = 0; t < 4; t++) {
            uint32_t ah[4], alr[4];
            split2(sacc[2*t][0],   sacc[2*t][1],   ah[0], alr[0]);
            split2(sacc[2*t][2],   sacc[2*t][3],   ah[1], alr[1]);
            split2(sacc[2*t+1][0], sacc[2*t+1][1], ah[2], alr[2]);
            split2(sacc[2*t+1][2], sacc[2*t+1][3], ah[3], alr[3]);
            #pragma unroll
            for (int u = 0; u < 4; u++) {
                int row = t * 16 + (lane & 7) + 8 * ((lane >> 3) & 1);
                int coln = u * 16 + 8 * (lane >> 4);
                uint32_t boff = (row * FPH + coln) * 2;
                uint32_t vh[4], vl[4];
                ldsm_x4t(aVh + boff, vh[0], vh[1], vh[2], vh[3]);
                ldsm_x4t(aVl + boff, vl[0], vl[1], vl[2], vl[3]);
                mma_bf16(oacc[2*u],   ah,  vh[0], vh[1]);
                mma_bf16(oacc[2*u],   ah,  vl[0], vl[1]);
                mma_bf16(oacc[2*u],   alr, vh[0], vh[1]);
                mma_bf16(oacc[2*u+1], ah,  vh[2], vh[3]);
                mma_bf16(oacc[2*u+1], ah,  vl[2], vl[3]);
                mma_bf16(oacc[2*u+1], alr, vh[2], vh[3]);
            }
        }
    }

    // ---- epilogue: O /= l, split to bf16 hi/lo ----
    float i0 = 1.f / lr0, i1 = 1.f / lr1;
    #pragma unroll
    for (int t = 0; t < 8; t++) {
        int col = colbase + t * 8 + 2 * (lane & 3);
        size_t o0 = (rowbase + q0 + w * 16 + (lane >> 2)) * EMB + col;
        size_t o1 = o0 + 8 * EMB;
        uint32_t h, l;
        split2(oacc[t][0] * i0, oacc[t][1] * i0, h, l);
        *(uint32_t*)(Oh + o0) = h;
        *(uint32_t*)(Ol + o0) = l;
        split2(oacc[t][2] * i1, oacc[t][3] * i1, h, l);
        *(uint32_t*)(Oh + o1) = h;
        *(uint32_t*)(Ol + o1) = l;
    }
}

// ---------------------------------------------------------------------------
extern "C" void kernel_launch(void* const* d_in, const int* in_sizes, int n_in,
                              void* d_out, int out_size)
{
    const float* x  = (const float*)d_in[0];
    const int*   am = (const int*)d_in[1];
    const float* w[4] = { (const float*)d_in[2], (const float*)d_in[3],
                          (const float*)d_in[4], (const float*)d_in[5] };
    float* out = (float*)d_out;

    __nv_bfloat16 *xh, *xl, *wh, *wl, *Qh, *Ql, *Kh, *Kl, *Vh, *Vl, *Oh, *Ol;
    cudaGetSymbolAddress((void**)&xh, g_xh);
    cudaGetSymbolAddress((void**)&xl, g_xl);
    cudaGetSymbolAddress((void**)&wh, g_wh);
    cudaGetSymbolAddress((void**)&wl, g_wl);
    cudaGetSymbolAddress((void**)&Qh, g_Qh);
    cudaGetSymbolAddress((void**)&Ql, g_Ql);
    cudaGetSymbolAddress((void**)&Kh, g_Kh);
    cudaGetSymbolAddress((void**)&Kl, g_Kl);
    cudaGetSymbolAddress((void**)&Vh, g_Vh);
    cudaGetSymbolAddress((void**)&Vl, g_Vl);
    cudaGetSymbolAddress((void**)&Oh, g_Oh);
    cudaGetSymbolAddress((void**)&Ol, g_Ol);

    cudaFuncSetAttribute(gemm_tc, cudaFuncAttributeMaxDynamicSharedMemorySize, GEMM_SMEM);
    cudaFuncSetAttribute(flash_tc, cudaFuncAttributeMaxDynamicSharedMemorySize, FLASH_SMEM);

    split_k<<<(NTOK * EMB / 4 + 255) / 256, 256>>>(x, xh, xl, NTOK * EMB / 4);
    for (int i = 0; i < 4; i++)
        split_k<<<(EMB * EMB / 4 + 255) / 256, 256>>>(
            w[i], wh + (size_t)i * EMB * EMB, wl + (size_t)i * EMB * EMB, EMB * EMB / 4);

    dim3 ggrid(EMB / 128, NTOK / 128);
    gemm_tc<<<ggrid, 256, GEMM_SMEM>>>(xh, xl, wh + 0 * (size_t)EMB * EMB,
                                       wl + 0 * (size_t)EMB * EMB, nullptr, Qh, Ql);
    gemm_tc<<<ggrid, 256, GEMM_SMEM>>>(xh, xl, wh + 1 * (size_t)EMB * EMB,
                                       wl + 1 * (size_t)EMB * EMB, nullptr, Kh, Kl);
    gemm_tc<<<ggrid, 256, GEMM_SMEM>>>(xh, xl, wh + 2 * (size_t)EMB * EMB,
                                       wl + 2 * (size_t)EMB * EMB, nullptr, Vh, Vl);

    flash_tc<<<dim3(S_LEN / 128, NH, BATCH), 256, FLASH_SMEM>>>(
        Qh, Ql, Kh, Kl, Vh, Vl, am, Oh, Ol);

    gemm_tc<<<ggrid, 256, GEMM_SMEM>>>(Oh, Ol, wh + 3 * (size_t)EMB * EMB,
                                       wl + 3 * (size_t)EMB * EMB, out, nullptr, nullptr);
}

// round 8
// speedup vs baseline: 2.8677x; 1.0458x over previous
#include <cuda_runtime.h>
#include <cuda_bf16.h>
#include <cstdint>
#include <math.h>

#define S_LEN 2048
#define BATCH 4
#define EMB   1024
#define NH    16
#define HD    64
#define NTOK  (BATCH * S_LEN)   // 8192

// ---------------- scratch (device globals; no allocs allowed) --------------
__device__ __nv_bfloat16 g_xh[NTOK * EMB];
__device__ __nv_bfloat16 g_xl[NTOK * EMB];
__device__ __nv_bfloat16 g_wh[4][EMB * EMB];
__device__ __nv_bfloat16 g_wl[4][EMB * EMB];
__device__ __nv_bfloat16 g_Qh[NTOK * EMB];
__device__ __nv_bfloat16 g_Ql[NTOK * EMB];
__device__ __nv_bfloat16 g_Kh[NTOK * EMB];
__device__ __nv_bfloat16 g_Kl[NTOK * EMB];
__device__ __nv_bfloat16 g_Vh[NTOK * EMB];
__device__ __nv_bfloat16 g_Vl[NTOK * EMB];
__device__ __nv_bfloat16 g_Oh[NTOK * EMB];
__device__ __nv_bfloat16 g_Ol[NTOK * EMB];

// ---------------- helpers --------------------------------------------------
__device__ __forceinline__ uint32_t smem_u32(const void* p) {
    uint32_t a;
    asm("{ .reg .u64 t; cvta.to.shared.u64 t, %1; cvt.u32.u64 %0, t; }" : "=r"(a) : "l"(p));
    return a;
}
__device__ __forceinline__ void ldsm_x4(uint32_t a, uint32_t& r0, uint32_t& r1,
                                        uint32_t& r2, uint32_t& r3) {
    asm volatile("ldmatrix.sync.aligned.m8n8.x4.shared.b16 {%0,%1,%2,%3}, [%4];"
                 : "=r"(r0), "=r"(r1), "=r"(r2), "=r"(r3) : "r"(a));
}
__device__ __forceinline__ void ldsm_x4t(uint32_t a, uint32_t& r0, uint32_t& r1,
                                         uint32_t& r2, uint32_t& r3) {
    asm volatile("ldmatrix.sync.aligned.m8n8.x4.trans.shared.b16 {%0,%1,%2,%3}, [%4];"
                 : "=r"(r0), "=r"(r1), "=r"(r2), "=r"(r3) : "r"(a));
}
__device__ __forceinline__ void mma_bf16(float* d, const uint32_t* a,
                                         uint32_t b0, uint32_t b1) {
    asm volatile(
        "mma.sync.aligned.m16n8k16.row.col.f32.bf16.bf16.f32 "
        "{%0,%1,%2,%3}, {%4,%5,%6,%7}, {%8,%9}, {%0,%1,%2,%3};"
        : "+f"(d[0]), "+f"(d[1]), "+f"(d[2]), "+f"(d[3])
        : "r"(a[0]), "r"(a[1]), "r"(a[2]), "r"(a[3]), "r"(b0), "r"(b1));
}
__device__ __forceinline__ void split2(float x, float y, uint32_t& hi, uint32_t& lo) {
    __nv_bfloat162 h = __floats2bfloat162_rn(x, y);
    hi = *(uint32_t*)&h;
    __nv_bfloat162 l = __floats2bfloat162_rn(x - __bfloat162float(h.x),
                                             y - __bfloat162float(h.y));
    lo = *(uint32_t*)&l;
}
#define CP_ASYNC16(s, g) \
    asm volatile("cp.async.cg.shared.global [%0], [%1], 16;" :: "r"(s), "l"(g) : "memory")
#define CP_COMMIT() asm volatile("cp.async.commit_group;" ::: "memory")
#define CP_WAIT0()  asm volatile("cp.async.wait_group 0;" ::: "memory")

// ---------------------------------------------------------------------------
// split fp32 -> (hi, lo) bf16
// ---------------------------------------------------------------------------
__global__ __launch_bounds__(256) void split_k(
    const float* __restrict__ src, __nv_bfloat16* __restrict__ hi,
    __nv_bfloat16* __restrict__ lo, int n4)
{
    int i = blockIdx.x * 256 + threadIdx.x;
    if (i >= n4) return;
    float4 v = ((const float4*)src)[i];
    float x[4] = {v.x, v.y, v.z, v.w};
    __nv_bfloat16 h[4], l[4];
    #pragma unroll
    for (int j = 0; j < 4; j++) {
        h[j] = __float2bfloat16_rn(x[j]);
        l[j] = __float2bfloat16_rn(x[j] - __bfloat162float(h[j]));
    }
    ((uint2*)hi)[i] = *(uint2*)h;
    ((uint2*)lo)[i] = *(uint2*)l;
}

// ---------------------------------------------------------------------------
// mma.sync split-bf16 GEMM: C[M,N] = A @ W_z^T.  CTA 128x128, K chunk 64,
// 2-stage cp.async, ONE barrier per chunk, pitch 72 (conflict-free ldsm).
// blockIdx.z selects weight z and bf16 hi/lo output z; Cf!=null -> fp32 out.
// ---------------------------------------------------------------------------
#define GP 72
#define GTILE_H (128 * GP)            // 9216 halves
#define GSTAGE_H (4 * GTILE_H)        // 36864 halves
#define GEMM_SMEM (2 * GSTAGE_H * 2)  // 147456 bytes

__global__ __launch_bounds__(256) void gemm_tc(
    const __nv_bfloat16* __restrict__ Ah, const __nv_bfloat16* __restrict__ Al,
    const __nv_bfloat16* __restrict__ WhB, const __nv_bfloat16* __restrict__ WlB,
    float* __restrict__ Cf,
    __nv_bfloat16* __restrict__ C0h, __nv_bfloat16* __restrict__ C0l,
    __nv_bfloat16* __restrict__ C1h, __nv_bfloat16* __restrict__ C1l,
    __nv_bfloat16* __restrict__ C2h, __nv_bfloat16* __restrict__ C2l)
{
    extern __shared__ __nv_bfloat16 sm[];
    const uint32_t sb = smem_u32(sm);
    const int tid = threadIdx.x, lane = tid & 31, w = tid >> 5;
    const int wm = w & 1, wn = w >> 1;
    const int m0 = blockIdx.y * 128, n0 = blockIdx.x * 128;
    const int z = blockIdx.z;
    const __nv_bfloat16* Bh = WhB + (size_t)z * EMB * EMB;
    const __nv_bfloat16* Bl = WlB + (size_t)z * EMB * EMB;
    __nv_bfloat16* Ch = (z == 0) ? C0h : (z == 1) ? C1h : C2h;
    __nv_bfloat16* Cl = (z == 0) ? C0l : (z == 1) ? C1l : C2l;

    const __nv_bfloat16* srcs[4] = {Ah, Al, Bh, Bl};
    const int r0s[4] = {m0, m0, n0, n0};

    auto issue = [&](int k0, int st) {
        #pragma unroll
        for (int i = 0; i < 16; i++) {
            int idx = i * 256 + tid;
            int t = idx >> 10, j = idx & 1023;
            int row = j >> 3, c8 = (j & 7) * 8;
            const __nv_bfloat16* g = srcs[t] + (size_t)(r0s[t] + row) * EMB + k0 + c8;
            uint32_t s = sb + (uint32_t)(st * GSTAGE_H + t * GTILE_H + row * GP + c8) * 2;
            CP_ASYNC16(s, g);
        }
        CP_COMMIT();
    };

    issue(0, 0);
    float acc[4][4][4] = {};

    for (int c = 0; c < 16; c++) {
        const int st = c & 1;
        CP_WAIT0();
        __syncthreads();
        if (c + 1 < 16) issue((c + 1) * 64, st ^ 1);

        const uint32_t abase = sb + (st * GSTAGE_H) * 2;
        const uint32_t bbase = sb + (st * GSTAGE_H + 2 * GTILE_H) * 2;
        #pragma unroll
        for (int kc = 0; kc < 4; kc++) {
            uint32_t af[4][4], alf[4][4], bf[2][4], blf[2][4];
            #pragma unroll
            for (int mt = 0; mt < 4; mt++) {
                int row = wm * 64 + mt * 16 + (lane & 15);
                uint32_t a = abase + (row * GP + kc * 16 + 8 * (lane >> 4)) * 2;
                ldsm_x4(a, af[mt][0], af[mt][1], af[mt][2], af[mt][3]);
                ldsm_x4(a + GTILE_H * 2, alf[mt][0], alf[mt][1], alf[mt][2], alf[mt][3]);
            }
            #pragma unroll
            for (int u = 0; u < 2; u++) {
                int row = wn * 32 + u * 16 + (lane & 7) + 8 * ((lane >> 3) & 1);
                uint32_t b = bbase + (row * GP + kc * 16 + 8 * (lane >> 4)) * 2;
                ldsm_x4(b, bf[u][0], bf[u][1], bf[u][2], bf[u][3]);
                ldsm_x4(b + GTILE_H * 2, blf[u][0], blf[u][1], blf[u][2], blf[u][3]);
            }
            #pragma unroll
            for (int mt = 0; mt < 4; mt++)
                #pragma unroll
                for (int u = 0; u < 2; u++) {
                    mma_bf16(acc[mt][2*u],   af[mt],  bf[u][0],  bf[u][2]);
                    mma_bf16(acc[mt][2*u],   af[mt],  blf[u][0], blf[u][2]);
                    mma_bf16(acc[mt][2*u],   alf[mt], bf[u][0],  bf[u][2]);
                    mma_bf16(acc[mt][2*u+1], af[mt],  bf[u][1],  bf[u][3]);
                    mma_bf16(acc[mt][2*u+1], af[mt],  blf[u][1], blf[u][3]);
                    mma_bf16(acc[mt][2*u+1], alf[mt], bf[u][1],  bf[u][3]);
                }
        }
        __syncthreads();
    }

    #pragma unroll
    for (int mt = 0; mt < 4; mt++) {
        int grow = m0 + wm * 64 + mt * 16 + (lane >> 2);
        #pragma unroll
        for (int nt = 0; nt < 4; nt++) {
            int gcol = n0 + wn * 32 + nt * 8 + 2 * (lane & 3);
            float* a = acc[mt][nt];
            if (Cf) {
                *(float2*)(Cf + (size_t)grow * EMB + gcol) = make_float2(a[0], a[1]);
                *(float2*)(Cf + (size_t)(grow + 8) * EMB + gcol) = make_float2(a[2], a[3]);
            } else {
                uint32_t h, l;
                split2(a[0], a[1], h, l);
                *(uint32_t*)(Ch + (size_t)grow * EMB + gcol) = h;
                *(uint32_t*)(Cl + (size_t)grow * EMB + gcol) = l;
                split2(a[2], a[3], h, l);
                *(uint32_t*)(Ch + (size_t)(grow + 8) * EMB + gcol) = h;
                *(uint32_t*)(Cl + (size_t)(grow + 8) * EMB + gcol) = l;
            }
        }
    }
}

// ---------------------------------------------------------------------------
// Flash attention, mma.sync split-bf16, cp.async 2-stage K/V/mask pipeline,
// one barrier per tile, qt-descending remap, per-warp masked-tile skip.
// ---------------------------------------------------------------------------
#define FPH 72
#define FQ_H (128 * FPH)              // 9216 halves
#define FK_H (64 * FPH)               // 4608 halves
#define FSTG_H (4 * FK_H)             // 18432 halves per stage (Kh,Kl,Vh,Vl)
#define FLASH_SMEM ((2 * FQ_H + 2 * FSTG_H) * 2 + 2 * 64 * 4)   // 111104 B

__global__ __launch_bounds__(256) void flash_tc(
    const __nv_bfloat16* __restrict__ Qh, const __nv_bfloat16* __restrict__ Ql,
    const __nv_bfloat16* __restrict__ Kh, const __nv_bfloat16* __restrict__ Kl,
    const __nv_bfloat16* __restrict__ Vh, const __nv_bfloat16* __restrict__ Vl,
    const int* __restrict__ am,
    __nv_bfloat16* __restrict__ Oh, __nv_bfloat16* __restrict__ Ol)
{
    extern __shared__ __nv_bfloat16 sm[];
    const uint32_t sb = smem_u32(sm);
    int* ambuf = (int*)(sm + 2 * FQ_H + 2 * FSTG_H);

    const int tid = threadIdx.x, lane = tid & 31, w = tid >> 5;
    const int qt = (int)(gridDim.x - 1 - blockIdx.x);   // heavy tiles first
    const int q0 = qt * 128;
    const size_t rowbase = (size_t)blockIdx.z * S_LEN;
    const int colbase = blockIdx.y * HD;

    const __nv_bfloat16* srcs[4] = {Kh, Kl, Vh, Vl};

    auto prefetch = [&](int kt, int st) {
        const int k0 = kt * 64;
        #pragma unroll
        for (int i = 0; i < 8; i++) {
            int idx = i * 256 + tid;
            int t = idx >> 9, j = idx & 511;
            int row = j >> 3, c8 = (j & 7) * 8;
            const __nv_bfloat16* g = srcs[t] + (rowbase + k0 + row) * EMB + colbase + c8;
            uint32_t s = sb + (uint32_t)(2 * FQ_H + st * FSTG_H + t * FK_H + row * FPH + c8) * 2;
            CP_ASYNC16(s, g);
        }
        if (tid < 16) {
            const int* g = am + rowbase + k0 + tid * 4;
            uint32_t s = sb + (uint32_t)(2 * FQ_H + 2 * FSTG_H) * 2 + (st * 64 + tid * 4) * 4;
            CP_ASYNC16(s, g);
        }
        CP_COMMIT();
    };

    // Q tile (hi + lo), plain loads
    #pragma unroll
    for (int i = 0; i < 4; i++) {
        int idx = i * 256 + tid;
        int row = idx >> 3, c8 = (idx & 7) * 8;
        size_t go = (rowbase + q0 + row) * EMB + colbase + c8;
        *(float4*)&sm[row * FPH + c8]        = *(const float4*)&Qh[go];
        *(float4*)&sm[FQ_H + row * FPH + c8] = *(const float4*)&Ql[go];
    }
    prefetch(0, 0);

    float oacc[8][4] = {};
    float mr0 = -1e30f, mr1 = -1e30f, lr0 = 0.f, lr1 = 0.f;

    const uint32_t aQh = sb, aQl = sb + FQ_H * 2;
    const int qrow  = q0 + w * 16 + (lane >> 2);
    const int qmaxw = q0 + w * 16 + 15;
    const int nkt = 2 * qt + 2;

    for (int kt = 0; kt < nkt; kt++) {
        const int k0 = kt * 64;
        const int st = kt & 1;
        CP_WAIT0();
        __syncthreads();
        if (kt + 1 < nkt) prefetch(kt + 1, st ^ 1);

        if (k0 > qmaxw) continue;   // fully masked for this warp

        const uint32_t aKh = sb + (uint32_t)(2 * FQ_H + st * FSTG_H) * 2;
        const uint32_t aKl = aKh + FK_H * 2;
        const uint32_t aVh = aKl + FK_H * 2;
        const uint32_t aVl = aVh + FK_H * 2;
        const int* amb = ambuf + st * 64;

        // ---- S = Q @ K^T (3-term split) ----
        float sacc[8][4] = {};
        #pragma unroll
        for (int kc = 0; kc < 4; kc++) {
            uint32_t qa[4], qla[4];
            {
                int row = w * 16 + (lane & 15);
                uint32_t a = (row * FPH + kc * 16 + 8 * (lane >> 4)) * 2;
                ldsm_x4(aQh + a, qa[0], qa[1], qa[2], qa[3]);
                ldsm_x4(aQl + a, qla[0], qla[1], qla[2], qla[3]);
            }
            #pragma unroll
            for (int np = 0; np < 4; np++) {
                int row = np * 16 + (lane & 7) + 8 * ((lane >> 3) & 1);
                uint32_t boff = (row * FPH + kc * 16 + 8 * (lane >> 4)) * 2;
                uint32_t kh[4], kl[4];
                ldsm_x4(aKh + boff, kh[0], kh[1], kh[2], kh[3]);
                ldsm_x4(aKl + boff, kl[0], kl[1], kl[2], kl[3]);
                mma_bf16(sacc[2*np],   qa,  kh[0], kh[2]);
                mma_bf16(sacc[2*np],   qa,  kl[0], kl[2]);
                mma_bf16(sacc[2*np],   qla, kh[0], kh[2]);
                mma_bf16(sacc[2*np+1], qa,  kh[1], kh[3]);
                mma_bf16(sacc[2*np+1], qa,  kl[1], kl[3]);
                mma_bf16(sacc[2*np+1], qla, kh[1], kh[3]);
            }
        }

        // ---- online softmax in fragments ----
        const bool needmask = (k0 + 63) > (q0 + w * 16);
        float mx0 = -1e30f, mx1 = -1e30f;
        #pragma unroll
        for (int t = 0; t < 8; t++) {
            int lc = t * 8 + 2 * (lane & 3);
            int a0 = amb[lc], a1 = amb[lc + 1];
            float s0 = a0 ? sacc[t][0] * 0.125f : -1e30f;
            float s1 = a1 ? sacc[t][1] * 0.125f : -1e30f;
            float s2 = a0 ? sacc[t][2] * 0.125f : -1e30f;
            float s3 = a1 ? sacc[t][3] * 0.125f : -1e30f;
            if (needmask) {
                int cg = k0 + lc;
                if (cg > qrow)         s0 = -1e30f;
                if (cg + 1 > qrow)     s1 = -1e30f;
                if (cg > qrow + 8)     s2 = -1e30f;
                if (cg + 1 > qrow + 8) s3 = -1e30f;
            }
            sacc[t][0] = s0; sacc[t][1] = s1; sacc[t][2] = s2; sacc[t][3] = s3;
            mx0 = fmaxf(mx0, fmaxf(s0, s1));
            mx1 = fmaxf(mx1, fmaxf(s2, s3));
        }
        mx0 = fmaxf(mx0, __shfl_xor_sync(0xffffffffu, mx0, 1));
        mx0 = fmaxf(mx0, __shfl_xor_sync(0xffffffffu, mx0, 2));
        mx1 = fmaxf(mx1, __shfl_xor_sync(0xffffffffu, mx1, 1));
        mx1 = fmaxf(mx1, __shfl_xor_sync(0xffffffffu, mx1, 2));
        float mn0 = fmaxf(mr0, mx0), mn1 = fmaxf(mr1, mx1);
        float al0 = __expf(mr0 - mn0), al1 = __expf(mr1 - mn1);
        mr0 = mn0; mr1 = mn1;
        float sm0 = 0.f, sm1 = 0.f;
        #pragma unroll
        for (int t = 0; t < 8; t++) {
            float p0 = __expf(sacc[t][0] - mn0);
            float p1 = __expf(sacc[t][1] - mn0);
            float p2 = __expf(sacc[t][2] - mn1);
            float p3 = __expf(sacc[t][3] - mn1);
            sacc[t][0] = p0; sacc[t][1] = p1; sacc[t][2] = p2; sacc[t][3] = p3;
            sm0 += p0 + p1; sm1 += p2 + p3;
        }
        sm0 += __shfl_xor_sync(0xffffffffu, sm0, 1);
        sm0 += __shfl_xor_sync(0xffffffffu, sm0, 2);
        sm1 += __shfl_xor_sync(0xffffffffu, sm1, 1);
        sm1 += __shfl_xor_sync(0xffffffffu, sm1, 2);
        lr0 = lr0 * al0 + sm0;
        lr1 = lr1 * al1 + sm1;
        #pragma unroll
        for (int t = 0; t < 8; t++) {
            oacc[t][0] *= al0; oacc[t][1] *= al0;
            oacc[t][2] *= al1; oacc[t][3] *= al1;
        }

        // ---- O += P @ V (3-term split; P in registers) ----
        #pragma unroll
        for (int t = 0; t < 4; t++) {
            uint32_t ah[4], alr[4];
            split2(sacc[2*t][0],   sacc[2*t][1],   ah[0], alr[0]);
            split2(sacc[2*t][2],   sacc[2*t][3],   ah[1], alr[1]);
            split2(sacc[2*t+1][0], sacc[2*t+1][1], ah[2], alr[2]);
            split2(sacc[2*t+1][2], sacc[2*t+1][3], ah[3], alr[3]);
            #pragma unroll
            for (int u = 0; u < 4; u++) {
                int row = t * 16 + (lane & 7) + 8 * ((lane >> 3) & 1);
                int coln = u * 16 + 8 * (lane >> 4);
                uint32_t boff = (row * FPH + coln) * 2;
                uint32_t vh[4], vl[4];
                ldsm_x4t(aVh + boff, vh[0], vh[1], vh[2], vh[3]);
                ldsm_x4t(aVl + boff, vl[0], vl[1], vl[2], vl[3]);
                mma_bf16(oacc[2*u],   ah,  vh[0], vh[1]);
                mma_bf16(oacc[2*u],   ah,  vl[0], vl[1]);
                mma_bf16(oacc[2*u],   alr, vh[0], vh[1]);
                mma_bf16(oacc[2*u+1], ah,  vh[2], vh[3]);
                mma_bf16(oacc[2*u+1], ah,  vl[2], vl[3]);
                mma_bf16(oacc[2*u+1], alr, vh[2], vh[3]);
            }
        }
    }

    // ---- epilogue: O /= l, split to bf16 hi/lo ----
    float i0 = 1.f / lr0, i1 = 1.f / lr1;
    #pragma unroll
    for (int t = 0; t < 8; t++) {
        int col = colbase + t * 8 + 2 * (lane & 3);
        size_t o0 = (rowbase + q0 + w * 16 + (lane >> 2)) * EMB + col;
        size_t o1 = o0 + 8 * EMB;
        uint32_t h, l;
        split2(oacc[t][0] * i0, oacc[t][1] * i0, h, l);
        *(uint32_t*)(Oh + o0) = h;
        *(uint32_t*)(Ol + o0) = l;
        split2(oacc[t][2] * i1, oacc[t][3] * i1, h, l);
        *(uint32_t*)(Oh + o1) = h;
        *(uint32_t*)(Ol + o1) = l;
    }
}

// ---------------------------------------------------------------------------
extern "C" void kernel_launch(void* const* d_in, const int* in_sizes, int n_in,
                              void* d_out, int out_size)
{
    const float* x  = (const float*)d_in[0];
    const int*   am = (const int*)d_in[1];
    const float* w[4] = { (const float*)d_in[2], (const float*)d_in[3],
                          (const float*)d_in[4], (const float*)d_in[5] };
    float* out = (float*)d_out;

    __nv_bfloat16 *xh, *xl, *wh, *wl, *Qh, *Ql, *Kh, *Kl, *Vh, *Vl, *Oh, *Ol;
    cudaGetSymbolAddress((void**)&xh, g_xh);
    cudaGetSymbolAddress((void**)&xl, g_xl);
    cudaGetSymbolAddress((void**)&wh, g_wh);
    cudaGetSymbolAddress((void**)&wl, g_wl);
    cudaGetSymbolAddress((void**)&Qh, g_Qh);
    cudaGetSymbolAddress((void**)&Ql, g_Ql);
    cudaGetSymbolAddress((void**)&Kh, g_Kh);
    cudaGetSymbolAddress((void**)&Kl, g_Kl);
    cudaGetSymbolAddress((void**)&Vh, g_Vh);
    cudaGetSymbolAddress((void**)&Vl, g_Vl);
    cudaGetSymbolAddress((void**)&Oh, g_Oh);
    cudaGetSymbolAddress((void**)&Ol, g_Ol);

    cudaFuncSetAttribute(gemm_tc, cudaFuncAttributeMaxDynamicSharedMemorySize, GEMM_SMEM);
    cudaFuncSetAttribute(flash_tc, cudaFuncAttributeMaxDynamicSharedMemorySize, FLASH_SMEM);

    split_k<<<(NTOK * EMB / 4 + 255) / 256, 256>>>(x, xh, xl, NTOK * EMB / 4);
    for (int i = 0; i < 4; i++)
        split_k<<<(EMB * EMB / 4 + 255) / 256, 256>>>(
            w[i], wh + (size_t)i * EMB * EMB, wl + (size_t)i * EMB * EMB, EMB * EMB / 4);

    // fused Q/K/V projections (blockIdx.z selects weight + destination)
    gemm_tc<<<dim3(EMB / 128, NTOK / 128, 3), 256, GEMM_SMEM>>>(
        xh, xl, wh, wl, nullptr, Qh, Ql, Kh, Kl, Vh, Vl);

    flash_tc<<<dim3(S_LEN / 128, NH, BATCH), 256, FLASH_SMEM>>>(
        Qh, Ql, Kh, Kl, Vh, Vl, am, Oh, Ol);

    // output projection -> fp32
    gemm_tc<<<dim3(EMB / 128, NTOK / 128, 1), 256, GEMM_SMEM>>>(
        Oh, Ol, wh + 3 * (size_t)EMB * EMB, wl + 3 * (size_t)EMB * EMB,
        out, nullptr, nullptr, nullptr, nullptr, nullptr, nullptr);
}